// round 11
// baseline (speedup 1.0000x reference)
#include <cuda_runtime.h>
#include <math.h>

// ---------------------------------------------------------------------------
// SimpleNet quanvolutional pipeline, sm_103a
//   g_h1: [4][255][256]  (row stride 256)
//   g_h2: [20][125][128] (row stride 128)
// qconv: j-pair FFMA2 (no W duplication, no register blowup).
// conv2: quadrant-pair FFMA2 (R8 inner loop) with 2co z=10 grid.
// conv3: R10 best (tile shared across 4 co, double-buffered chunks).
// ---------------------------------------------------------------------------

typedef unsigned long long u64;

__device__ __forceinline__ u64 f2pack(float lo, float hi) {
    u64 r; asm("mov.b64 %0, {%1, %2};" : "=l"(r) : "f"(lo), "f"(hi)); return r;
}
__device__ __forceinline__ void f2unpack(u64 v, float& lo, float& hi) {
    asm("mov.b64 {%0, %1}, %2;" : "=f"(lo), "=f"(hi) : "l"(v));
}
__device__ __forceinline__ u64 f2fma(u64 a, u64 b, u64 c) {
    u64 d; asm("fma.rn.f32x2 %0, %1, %2, %3;" : "=l"(d) : "l"(a), "l"(b), "l"(c)); return d;
}

__device__ u64 g_Wr2[128];                 // [k][m]: (wr[k][2m], wr[k][2m+1])
__device__ u64 g_Wi2[128];                 // [k][m]: (wi[k][2m], wi[k][2m+1])
__device__ float g_h1[4 * 255 * 256];
__device__ float g_h2[20 * 125 * 128];
__device__ float g_bins[640];              // adaptive-max bins (atomicMax as int)

#define H1_STRIDE 256
#define H1_PLANE  (255 * 256)
#define H2_STRIDE 128
#define H2_PLANE  (125 * 128)

// ---------------------------------------------------------------------------
// k_prep: simulate weight circuit -> U; export W[k][j] = U[k][j]*(-i)^popc(j)
// as j-pair tables. Zero adaptive-max bins.
// ---------------------------------------------------------------------------
__global__ void k_prep(const float* __restrict__ qw) {
    int t = threadIdx.x;                 // 0..255
    for (int b = t; b < 640; b += 256) ((int*)g_bins)[b] = 0;

    __shared__ float Ur[16][16], Ui[16][16];

    if (t < 16) {
        int k = t;
        float pr[16], pi[16];
        #pragma unroll
        for (int i = 0; i < 16; i++) { pr[i] = (i == k) ? 1.f : 0.f; pi[i] = 0.f; }

        for (int l = 0; l < 3; l++) {
            for (int w = 0; w < 4; w++) {
                float phi = qw[(l * 4 + w) * 3 + 0];
                float th  = qw[(l * 4 + w) * 3 + 1];
                float om  = qw[(l * 4 + w) * 3 + 2];
                float st, ct, sap, cap, sam, cam;
                sincosf(0.5f * th, &st, &ct);
                sincosf(0.5f * (phi + om), &sap, &cap);
                sincosf(0.5f * (phi - om), &sam, &cam);
                float u00r =  cap * ct, u00i = -sap * ct;
                float u01r = -cam * st, u01i = -sam * st;
                float u10r =  cam * st, u10i = -sam * st;
                float u11r =  cap * ct, u11i =  sap * ct;
                int m = 8 >> w;
                for (int i0 = 0; i0 < 16; i0++) {
                    if (i0 & m) continue;
                    int i1 = i0 | m;
                    float a0r = pr[i0], a0i = pi[i0];
                    float a1r = pr[i1], a1i = pi[i1];
                    pr[i0] = u00r * a0r - u00i * a0i + u01r * a1r - u01i * a1i;
                    pi[i0] = u00r * a0i + u00i * a0r + u01r * a1i + u01i * a1r;
                    pr[i1] = u10r * a0r - u10i * a0i + u11r * a1r - u11i * a1i;
                    pi[i1] = u10r * a0i + u10i * a0r + u11r * a1i + u11i * a1r;
                }
            }
            int r = l % 3 + 1;
            for (int w = 0; w < 4; w++) {
                int cm = 8 >> w;
                int tm = 8 >> ((w + r) & 3);
                for (int i = 0; i < 16; i++) {
                    if ((i & cm) && !(i & tm)) {
                        int j = i | tm;
                        float tr = pr[i], ti = pi[i];
                        pr[i] = pr[j]; pi[i] = pi[j];
                        pr[j] = tr;    pi[j] = ti;
                    }
                }
            }
        }
        #pragma unroll
        for (int i = 0; i < 16; i++) { Ur[i][k] = pr[i]; Ui[i][k] = pi[i]; }
    }
    __syncthreads();

    if (t < 128) {
        int k = t >> 3, m = t & 7;
        float wr[2], wi[2];
        #pragma unroll
        for (int h = 0; h < 2; h++) {
            int j = 2 * m + h;
            float ur = Ur[k][j], ui = Ui[k][j];
            int d = __popc(j) & 3;
            wr[h] = (d == 0) ? ur : (d == 1) ? ui : (d == 2) ? -ur : -ui;
            wi[h] = (d == 0) ? ui : (d == 1) ? -ur : (d == 2) ? -ui : ur;
        }
        g_Wr2[t] = f2pack(wr[0], wr[1]);
        g_Wi2[t] = f2pack(wi[0], wi[1]);
    }
}

// ---------------------------------------------------------------------------
// k_qconv: j-pair FFMA2. psi_k dots computed in 2 lanes (j even/odd pairs),
// horizontal add at the end of each dot. 4 patches; ez; max-pool; sigmoid.
// ---------------------------------------------------------------------------
__global__ void __launch_bounds__(128) k_qconv(const float* __restrict__ img) {
    __shared__ __align__(16) u64 Wr2[128], Wi2[128];
    {
        int tid = threadIdx.y * 16 + threadIdx.x;
        if (tid < 128) { Wr2[tid] = g_Wr2[tid]; Wi2[tid] = g_Wi2[tid]; }
    }
    __syncthreads();

    int px = blockIdx.x * 16 + threadIdx.x;
    int py = blockIdx.y * 8 + threadIdx.y;
    if (px >= 255 || py >= 255) return;

    float cc[9], ss[9];
    int y0 = 2 * py, x0 = 2 * px;
    #pragma unroll
    for (int d = 0; d < 9; d++) {
        int dy = d / 3, dx = d % 3;
        float v = 0.5f * img[(y0 + dy) * 512 + (x0 + dx)];
        __sincosf(v, &ss[d], &cc[d]);
    }

    // r2[p][m] = (r[p][2m], r[p][2m+1]);  j = a*4+b -> m = a*2 + b/2
    u64 r2[4][8];
    #pragma unroll
    for (int p = 0; p < 4; p++) {
        int dy = p >> 1, dx = p & 1;
        int ia = dy * 3 + dx, ib = ia + 1, ic = ia + 3, id = ia + 4;
        float c0 = cc[ia], s0 = ss[ia], c1 = cc[ib], s1 = ss[ib];
        float c2 = cc[ic], s2 = ss[ic], c3 = cc[id], s3 = ss[id];
        float hi[4] = { c0 * c1, c0 * s1, s0 * c1, s0 * s1 };
        float lo[4] = { c2 * c3, c2 * s3, s2 * c3, s2 * s3 };
        #pragma unroll
        for (int a = 0; a < 4; a++) {
            r2[p][a * 2 + 0] = f2pack(hi[a] * lo[0], hi[a] * lo[1]);
            r2[p][a * 2 + 1] = f2pack(hi[a] * lo[2], hi[a] * lo[3]);
        }
    }

    float ez[4][4];
    #pragma unroll
    for (int p = 0; p < 4; p++)
        #pragma unroll
        for (int w = 0; w < 4; w++) ez[p][w] = 0.f;

    #pragma unroll
    for (int k = 0; k < 16; k++) {
        const ulonglong2* wr = (const ulonglong2*)&Wr2[k * 8];
        const ulonglong2* wi = (const ulonglong2*)&Wi2[k * 8];
        u64 sr2[4] = {0ull, 0ull, 0ull, 0ull};
        u64 si2[4] = {0ull, 0ull, 0ull, 0ull};
        #pragma unroll
        for (int m2 = 0; m2 < 4; m2++) {
            ulonglong2 a = wr[m2];
            ulonglong2 b = wi[m2];
            #pragma unroll
            for (int p = 0; p < 4; p++) {
                sr2[p] = f2fma(a.x, r2[p][2 * m2 + 0], sr2[p]);
                si2[p] = f2fma(b.x, r2[p][2 * m2 + 0], si2[p]);
                sr2[p] = f2fma(a.y, r2[p][2 * m2 + 1], sr2[p]);
                si2[p] = f2fma(b.y, r2[p][2 * m2 + 1], si2[p]);
            }
        }
        #pragma unroll
        for (int p = 0; p < 4; p++) {
            float e0, e1, f0, f1;
            f2unpack(sr2[p], e0, e1);
            f2unpack(si2[p], f0, f1);
            float sr = e0 + e1, si = f0 + f1;
            float pk = sr * sr + si * si;
            ez[p][0] += (k & 8) ? -pk : pk;
            ez[p][1] += (k & 4) ? -pk : pk;
            ez[p][2] += (k & 2) ? -pk : pk;
            ez[p][3] += (k & 1) ? -pk : pk;
        }
    }

    #pragma unroll
    for (int w = 0; w < 4; w++) {
        float m = fmaxf(fmaxf(ez[0][w], ez[1][w]), fmaxf(ez[2][w], ez[3][w]));
        g_h1[w * H1_PLANE + py * H1_STRIDE + px] = 1.f / (1.f + __expf(-m));
    }
}

// ---------------------------------------------------------------------------
// k_conv2: 5x5 conv (4->20) + relu + pool2 -> g_h2.
// 2 co per block (z=10), packed horizontal-pair FFMA2 inner loop (R8-proven).
// Block (16,8) covers 32x8 pooled px. Grid (4,16,10).
// ---------------------------------------------------------------------------
__global__ void __launch_bounds__(128) k_conv2(const float* __restrict__ w2,
                                               const float* __restrict__ b2) {
    int cog = blockIdx.z;                      // co = cog*2, cog*2+1
    __shared__ u64 ws2[2][100];                // duplicated (w,w)
    __shared__ __align__(16) float tile[4][20][68];
    int tx = threadIdx.x, ty = threadIdx.y;
    int tid = ty * 16 + tx;

    for (int q = tid; q < 200; q += 128) {
        int co = q / 100, rr = q % 100;
        float v = w2[(cog * 2 + co) * 100 + rr];
        ws2[co][rr] = f2pack(v, v);
    }

    int ix0 = blockIdx.x * 64, iy0 = blockIdx.y * 16;   // pre-pool origin
    for (int q = tid; q < 4 * 20 * 17; q += 128) {
        int ci = q / 340, rem = q % 340, ry = rem / 17, f4 = rem % 17;
        int gy = iy0 + ry, gx = ix0 + f4 * 4;
        float4 v = make_float4(0.f, 0.f, 0.f, 0.f);
        if (gy < 255) {
            const float* src = &g_h1[ci * H1_PLANE + gy * H1_STRIDE + gx];
            if (gx + 3 < 255) {
                v = *(const float4*)src;
            } else {
                if (gx + 0 < 255) v.x = src[0];
                if (gx + 1 < 255) v.y = src[1];
                if (gx + 2 < 255) v.z = src[2];
                if (gx + 3 < 255) v.w = src[3];
            }
        }
        *(float4*)&tile[ci][ry][f4 * 4] = v;
    }
    __syncthreads();

    // accT[co][pp] lanes = (top conv col c, col c+1); accB = bottom row
    u64 accT[2][2] = {{0ull, 0ull}, {0ull, 0ull}};
    u64 accB[2][2] = {{0ull, 0ull}, {0ull, 0ull}};

    int ly = 2 * ty, lx = 4 * tx;              // local pre-pool origin
    #pragma unroll
    for (int ci = 0; ci < 4; ci++) {
        float f[6][8];
        #pragma unroll
        for (int rr = 0; rr < 6; rr++) {
            const float4* rp = (const float4*)&tile[ci][ly + rr][lx];
            float4 v0 = rp[0], v1 = rp[1];
            f[rr][0] = v0.x; f[rr][1] = v0.y; f[rr][2] = v0.z; f[rr][3] = v0.w;
            f[rr][4] = v1.x; f[rr][5] = v1.y; f[rr][6] = v1.z; f[rr][7] = v1.w;
        }
        u64 pr[6][7];
        #pragma unroll
        for (int rr = 0; rr < 6; rr++)
            #pragma unroll
            for (int c = 0; c < 7; c++) pr[rr][c] = f2pack(f[rr][c], f[rr][c + 1]);

        #pragma unroll
        for (int co = 0; co < 2; co++) {
            #pragma unroll
            for (int ky = 0; ky < 5; ky++) {
                #pragma unroll
                for (int kx = 0; kx < 5; kx++) {
                    u64 wv = ws2[co][ci * 25 + ky * 5 + kx];
                    #pragma unroll
                    for (int pp = 0; pp < 2; pp++) {
                        int c = 2 * pp + kx;
                        accT[co][pp] = f2fma(wv, pr[ky][c], accT[co][pp]);
                        accB[co][pp] = f2fma(wv, pr[ky + 1][c], accB[co][pp]);
                    }
                }
            }
        }
    }

    int py = blockIdx.y * 8 + ty;
    #pragma unroll
    for (int co = 0; co < 2; co++) {
        float bb = b2[cog * 2 + co];
        #pragma unroll
        for (int pp = 0; pp < 2; pp++) {
            int px = blockIdx.x * 32 + 2 * tx + pp;
            if (px >= 125 || py >= 125) continue;
            float a0, a1, a2, a3;
            f2unpack(accT[co][pp], a0, a1);
            f2unpack(accB[co][pp], a2, a3);
            float m = fmaxf(fmaxf(a0, a1), fmaxf(a2, a3));
            m = fmaxf(m + bb, 0.f);
            g_h2[(cog * 2 + co) * H2_PLANE + py * H2_STRIDE + px] = m;
        }
    }
}

// ---------------------------------------------------------------------------
// k_conv3: 3x3 conv (20->40) + relu + adaptive-max.  (R10 best.)
// Block (16,16): two ty-halves = two co-pairs sharing one double-buffered
// tile. Thread: 2 horiz px; f32x2 lanes = co pair. Grid (4,16,10).
// Bins over 123: bin b = [floor(b*123/4), ceil((b+1)*123/4)); overlap rows
// 30,61,92 also belong to the NEXT bin.
// ---------------------------------------------------------------------------
__global__ void __launch_bounds__(256) k_conv3(const float* __restrict__ w3,
                                               const float* __restrict__ b3) {
    int cog2 = blockIdx.z;                     // co base = cog2*4
    __shared__ u64 ws2[2][180];                // [half] (w_co0, w_co1)
    __shared__ __align__(16) float tile[2][5][10][36];
    __shared__ int sbins[4][16];
    int tx = threadIdx.x, ty = threadIdx.y;
    int tid = ty * 16 + tx;
    int half = ty >> 3;                        // 0/1 -> co pair
    int tyl  = ty & 7;                         // row within 8-row band

    for (int q = tid; q < 360; q += 256) {
        int h = q / 180, rr = q % 180;
        ws2[h][rr] = f2pack(w3[(cog2 * 4 + h * 2 + 0) * 180 + rr],
                            w3[(cog2 * 4 + h * 2 + 1) * 180 + rr]);
    }
    if (tid < 64) ((int*)sbins)[tid] = 0;

    int px0 = blockIdx.x * 32, py0 = blockIdx.y * 8;
    int lx = 2 * tx;

    auto fill = [&](int c, int b) {
        for (int q = tid; q < 450; q += 256) {
            int cil = q / 90, rem = q % 90, ry = rem / 9, f4 = rem % 9;
            int gy = py0 + ry, gx = px0 + f4 * 4;
            float4 v = make_float4(0.f, 0.f, 0.f, 0.f);
            if (gy < 125 && gx < 125) {
                const float* src = &g_h2[(c * 5 + cil) * H2_PLANE + gy * H2_STRIDE + gx];
                if (gx + 3 < 125) {
                    v = *(const float4*)src;
                } else {
                    v.x = src[0];
                    if (gx + 1 < 125) v.y = src[1];
                    if (gx + 2 < 125) v.z = src[2];
                }
            }
            *(float4*)&tile[b][cil][ry][f4 * 4] = v;
        }
    };

    fill(0, 0);
    __syncthreads();

    u64 acc2[2] = {0ull, 0ull};                // 2 px, lanes = co pair

    for (int c4 = 0; c4 < 4; c4++) {
        int buf = c4 & 1;
        if (c4 < 3) fill(c4 + 1, buf ^ 1);     // overlap next chunk's loads

        #pragma unroll
        for (int cil = 0; cil < 5; cil++) {
            int ci = c4 * 5 + cil;
            float f[3][4];
            #pragma unroll
            for (int rr = 0; rr < 3; rr++) {
                const float2* rp = (const float2*)&tile[buf][cil][tyl + rr][lx];
                float2 v0 = rp[0], v1 = rp[1];
                f[rr][0] = v0.x; f[rr][1] = v0.y;
                f[rr][2] = v1.x; f[rr][3] = v1.y;
            }
            u64 p2[3][4];
            #pragma unroll
            for (int rr = 0; rr < 3; rr++)
                #pragma unroll
                for (int c = 0; c < 4; c++) p2[rr][c] = f2pack(f[rr][c], f[rr][c]);

            #pragma unroll
            for (int ky = 0; ky < 3; ky++) {
                #pragma unroll
                for (int kx = 0; kx < 3; kx++) {
                    u64 wv = ws2[half][ci * 9 + ky * 3 + kx];
                    acc2[0] = f2fma(wv, p2[ky][kx], acc2[0]);
                    acc2[1] = f2fma(wv, p2[ky][kx + 1], acc2[1]);
                }
            }
        }
        __syncthreads();
    }

    int gy = py0 + tyl;
    if (gy < 123) {
        int bi = (gy * 4) / 123; if (bi > 3) bi = 3;
        bool oy = (bi < 3) && (gy >= (((bi + 1) * 123) >> 2));
        float bb0 = b3[cog2 * 4 + half * 2 + 0];
        float bb1 = b3[cog2 * 4 + half * 2 + 1];
        int r0 = half * 2, r1 = half * 2 + 1;
        #pragma unroll
        for (int dx = 0; dx < 2; dx++) {
            int gx = px0 + lx + dx;
            if (gx >= 123) continue;
            float a0, a1;
            f2unpack(acc2[dx], a0, a1);
            float v0 = fmaxf(a0 + bb0, 0.f);
            float v1 = fmaxf(a1 + bb1, 0.f);
            int iv0 = __float_as_int(v0), iv1 = __float_as_int(v1);
            int bj = (gx * 4) / 123; if (bj > 3) bj = 3;
            bool ox = (bj < 3) && (gx >= (((bj + 1) * 123) >> 2));
            atomicMax(&sbins[r0][bi * 4 + bj], iv0);
            atomicMax(&sbins[r1][bi * 4 + bj], iv1);
            if (oy) { atomicMax(&sbins[r0][(bi + 1) * 4 + bj], iv0);
                      atomicMax(&sbins[r1][(bi + 1) * 4 + bj], iv1); }
            if (ox) { atomicMax(&sbins[r0][bi * 4 + (bj + 1)], iv0);
                      atomicMax(&sbins[r1][bi * 4 + (bj + 1)], iv1); }
            if (oy && ox) { atomicMax(&sbins[r0][(bi + 1) * 4 + (bj + 1)], iv0);
                            atomicMax(&sbins[r1][(bi + 1) * 4 + (bj + 1)], iv1); }
        }
    }
    __syncthreads();
    if (tid < 64) {
        int co = tid >> 4, b = tid & 15;
        atomicMax((int*)&g_bins[(cog2 * 4 + co) * 16 + b], sbins[co][b]);
    }
}

// ---------------------------------------------------------------------------
// k_fc: 640 -> 64 (relu) -> 10. One block, 256 threads (8 warps).
// ---------------------------------------------------------------------------
__global__ void __launch_bounds__(256) k_fc(const float* __restrict__ w1,
                                            const float* __restrict__ b1,
                                            const float* __restrict__ w2,
                                            const float* __restrict__ b2,
                                            float* __restrict__ out) {
    __shared__ float h[640];
    __shared__ float f1[64];
    int t = threadIdx.x;
    for (int i = t; i < 640; i += 256) h[i] = g_bins[i];
    __syncthreads();

    int warp = t >> 5, lane = t & 31;
    #pragma unroll
    for (int k = 0; k < 8; k++) {
        int n = warp * 8 + k;
        float s = 0.f;
        for (int j = lane; j < 640; j += 32) s += w1[n * 640 + j] * h[j];
        s += __shfl_xor_sync(0xffffffffu, s, 16);
        s += __shfl_xor_sync(0xffffffffu, s, 8);
        s += __shfl_xor_sync(0xffffffffu, s, 4);
        s += __shfl_xor_sync(0xffffffffu, s, 2);
        s += __shfl_xor_sync(0xffffffffu, s, 1);
        if (lane == 0) f1[n] = fmaxf(s + b1[n], 0.f);
    }
    __syncthreads();
    if (t < 10) {
        float a = b2[t];
        #pragma unroll
        for (int j = 0; j < 64; j++) a += w2[t * 64 + j] * f1[j];
        out[t] = a;
    }
}

// ---------------------------------------------------------------------------
extern "C" void kernel_launch(void* const* d_in, const int* in_sizes, int n_in,
                              void* d_out, int out_size) {
    const float* x   = (const float*)d_in[0];
    const float* qw  = (const float*)d_in[1];
    const float* c2w = (const float*)d_in[2];
    const float* c2b = (const float*)d_in[3];
    const float* c3w = (const float*)d_in[4];
    const float* c3b = (const float*)d_in[5];
    const float* f1w = (const float*)d_in[6];
    const float* f1b = (const float*)d_in[7];
    const float* f2w = (const float*)d_in[8];
    const float* f2b = (const float*)d_in[9];

    k_prep<<<1, 256>>>(qw);

    dim3 bq(16, 8), gq(16, 32);
    k_qconv<<<gq, bq>>>(x);

    dim3 bc(16, 8);
    dim3 g2(4, 16, 10);
    k_conv2<<<g2, bc>>>(c2w, c2b);

    dim3 bc3(16, 16);
    dim3 g3(4, 16, 10);
    k_conv3<<<g3, bc3>>>(c3w, c3b);

    k_fc<<<1, 256>>>(f1w, f1b, f2w, f2b, (float*)d_out);
}